// round 17
// baseline (speedup 1.0000x reference)
#include <cuda_runtime.h>
#include <cuda_bf16.h>
#include <cstdint>

typedef __nv_bfloat16 bf16;

#define D_  512
#define B_  8
#define S_  2048
#define F_  2048
#define L_  4
#define BS_ (B_*S_)
#define D3_ (3*D_)

// ---------------- scratch (static device globals; no allocation) ----------------
__device__ __align__(256) float g_x [BS_*D_];            // f32 master activations
__device__ __align__(256) float g_r [BS_*D_];            // f32 residual-sum branch
__device__ __align__(256) float g_sc[(size_t)B_*S_*S_];  // f32 attention scores
__device__ __align__(256) bf16  g_xb[BS_*D_];            // bf16 operand copies
__device__ __align__(256) bf16  g_qkv[(size_t)BS_*D3_];  // fused QKV output [BS,1536]
__device__ __align__(256) bf16  g_tb[BS_*D_];
__device__ __align__(256) bf16  g_hb[(size_t)BS_*F_];
__device__ __align__(256) int8_t g_pq[(size_t)B_*S_*S_]; // s8 softmax probs
__device__ __align__(256) float  g_ps[BS_];              // P row scales
__device__ __align__(256) int8_t g_qq[BS_*D_];           // s8 Q rows
__device__ __align__(256) float  g_qs[BS_];
__device__ __align__(256) int8_t g_kq[BS_*D_];           // s8 K rows
__device__ __align__(256) float  g_ks[BS_];
__device__ __align__(256) int8_t g_vtq[(size_t)B_*D_*S_];// s8 V^T per batch [512][2048]
__device__ __align__(256) int    g_vcm[B_*D_];           // V col absmax (as int-float)
__device__ __align__(256) float  g_vs[B_*D_];            // V col scales
__device__ __align__(256) bf16  g_wqkv[(size_t)L_*D_*D3_]; // [L][512][1536] concat W{q,k,v}
__device__ __align__(256) float g_bqkv[L_*D3_];            // [L][1536] concat b{q,k,v}
__device__ __align__(256) bf16  g_wob[L_*D_*D_];
__device__ __align__(256) bf16  g_w1b[(size_t)L_*D_*F_];
__device__ __align__(256) bf16  g_w2b[(size_t)L_*D_*F_];

// ---------------- weight converts ----------------
__global__ void cvt_bf(const float* __restrict__ s, bf16* __restrict__ d)
{
    int i = blockIdx.x * 256 + threadIdx.x;
    d[i] = __float2bfloat16(s[i]);
}
__global__ void cvt_qkv_w(const float* __restrict__ wq, const float* __restrict__ wk,
                          const float* __restrict__ wv, bf16* __restrict__ d)
{
    int i = blockIdx.x * 256 + threadIdx.x;      // over L*D*D
    int l = i / (D_ * D_), rem = i % (D_ * D_);
    int k = rem / D_, n = rem % D_;
    size_t o = (size_t)l * D_ * D3_ + (size_t)k * D3_ + n;
    d[o]           = __float2bfloat16(wq[i]);
    d[o + D_]      = __float2bfloat16(wk[i]);
    d[o + 2 * D_]  = __float2bfloat16(wv[i]);
}
__global__ void cvt_qkv_b(const float* __restrict__ bq, const float* __restrict__ bk,
                          const float* __restrict__ bv, float* __restrict__ d)
{
    int i = blockIdx.x * 256 + threadIdx.x;      // over L*D
    int l = i / D_, n = i % D_;
    d[l * D3_ + n]          = bq[i];
    d[l * D3_ + D_ + n]     = bk[i];
    d[l * D3_ + 2 * D_ + n] = bv[i];
}

// ---------------- embedding + sinusoidal PE (f32 + bf16 out) ----------------
__global__ void embed_kernel(const int* __restrict__ tok,
                             const float* __restrict__ emb,
                             float* __restrict__ x, bf16* __restrict__ xb)
{
    int idx = blockIdx.x * blockDim.x + threadIdx.x;
    int d  = idx & (D_ - 1);
    int bs = idx >> 9;
    int s  = bs & (S_ - 1);
    int t  = tok[bs];
    float dv  = expf(-(float)(d & ~1) * (9.210340371976184f / (float)D_));
    float arg = (float)s * dv;
    float pe  = (d & 1) ? cosf(arg) : sinf(arg);
    float v = emb[(size_t)t * D_ + d] + pe;
    x[idx]  = v;
    xb[idx] = __float2bfloat16(v);
}

// ---------------- row quant (len 512): bf16 rows -> s8 + scale ----------------
__global__ __launch_bounds__(128)
void quant_rows(const bf16* __restrict__ src, long long stride, int off,
                int8_t* __restrict__ dst, float* __restrict__ scales)
{
    __shared__ float red[4];
    const long long row = blockIdx.x;
    const int tid = threadIdx.x, lane = tid & 31, wid = tid >> 5;
    const bf16* p = src + row * stride + off;
    float v[4], am = 0.f;
#pragma unroll
    for (int i = 0; i < 4; i++) {
        v[i] = __bfloat162float(p[tid + i * 128]);
        am = fmaxf(am, fabsf(v[i]));
    }
#pragma unroll
    for (int s = 16; s > 0; s >>= 1)
        am = fmaxf(am, __shfl_xor_sync(0xffffffffu, am, s));
    if (lane == 0) red[wid] = am;
    __syncthreads();
    am = fmaxf(fmaxf(red[0], red[1]), fmaxf(red[2], red[3]));
    am = fmaxf(am, 1e-20f);
    if (tid == 0) scales[row] = am * (1.f / 127.f);
    const float inv = 127.f / am;
#pragma unroll
    for (int i = 0; i < 4; i++) {
        int q = __float2int_rn(v[i] * inv);
        q = max(-127, min(127, q));
        dst[row * D_ + tid + i * 128] = (int8_t)q;
    }
}

// ---------------- V column absmax (atomic) ----------------
__global__ __launch_bounds__(256)
void vcolmax(const bf16* __restrict__ qkv, int* __restrict__ cm)
{
    const int b = blockIdx.y, r0 = blockIdx.x * 128;
    for (int c = threadIdx.x; c < D_; c += 256) {
        float m = 0.f;
        for (int r = 0; r < 128; r++)
            m = fmaxf(m, fabsf(__bfloat162float(
                qkv[((size_t)b * S_ + r0 + r) * D3_ + 2 * D_ + c])));
        atomicMax(cm + b * D_ + c, __float_as_int(m));
    }
}
__global__ void vscale_fin(const int* __restrict__ cm, float* __restrict__ vs)
{
    int i = blockIdx.x * 256 + threadIdx.x;
    vs[i] = fmaxf(__int_as_float(cm[i]), 1e-20f) * (1.f / 127.f);
}
// ---------------- V transpose + quant: qkv v-seg [b][s][n] -> vtq [b][n][s] s8 ----
__global__ __launch_bounds__(256)
void vtquant(const bf16* __restrict__ qkv, const int* __restrict__ cm,
             int8_t* __restrict__ vt)
{
    __shared__ bf16 t[64][65];
    __shared__ float sinv[64];
    const int s0 = blockIdx.x * 64, n0 = blockIdx.y * 64, b = blockIdx.z;
    const int tid = threadIdx.x;
    if (tid < 64)
        sinv[tid] = 127.f / fmaxf(__int_as_float(cm[b * D_ + n0 + tid]), 1e-20f);
#pragma unroll
    for (int p = 0; p < 16; p++) {
        int idx = tid + p * 256;
        int r = idx >> 6, c = idx & 63;
        t[r][c] = qkv[((size_t)b * S_ + s0 + r) * D3_ + 2 * D_ + n0 + c];
    }
    __syncthreads();
#pragma unroll
    for (int p = 0; p < 16; p++) {
        int idx = tid + p * 256;
        int r2 = idx >> 6, c2 = idx & 63;   // r2 = n-local, c2 = s-local
        int q = __float2int_rn(__bfloat162float(t[c2][r2]) * sinv[r2]);
        q = max(-127, min(127, q));
        vt[((size_t)b * D_ + n0 + r2) * S_ + s0 + c2] = (int8_t)q;
    }
}

// ============ GEMM common machinery ============
#define BM 128
#define BN 256
#define BK 64
#define STAGES 4
#define A_STAGE_BYTES (BM * 128)
#define B_STAGE_BYTES 32768
#define STG_BYTES (A_STAGE_BYTES + B_STAGE_BYTES)
#define SMEM_BYTES (STAGES * STG_BYTES)

__device__ __forceinline__ void cp16(uint32_t dst, const void* src) {
    asm volatile("cp.async.cg.shared.global [%0], [%1], 16;" :: "r"(dst), "l"(src));
}
__device__ __forceinline__ void ldsm4(uint32_t* r, uint32_t addr) {
    asm volatile("ldmatrix.sync.aligned.m8n8.x4.shared.b16 {%0,%1,%2,%3}, [%4];"
        : "=r"(r[0]), "=r"(r[1]), "=r"(r[2]), "=r"(r[3]) : "r"(addr));
}
__device__ __forceinline__ void ldsm4t(uint32_t* r, uint32_t addr) {
    asm volatile("ldmatrix.sync.aligned.m8n8.x4.trans.shared.b16 {%0,%1,%2,%3}, [%4];"
        : "=r"(r[0]), "=r"(r[1]), "=r"(r[2]), "=r"(r[3]) : "r"(addr));
}
__device__ __forceinline__ void mma16(float* c, const uint32_t* a, const uint32_t* b) {
    asm volatile(
        "mma.sync.aligned.m16n8k16.row.col.f32.bf16.bf16.f32 "
        "{%0,%1,%2,%3},{%4,%5,%6,%7},{%8,%9},{%0,%1,%2,%3};"
        : "+f"(c[0]), "+f"(c[1]), "+f"(c[2]), "+f"(c[3])
        : "r"(a[0]), "r"(a[1]), "r"(a[2]), "r"(a[3]), "r"(b[0]), "r"(b[1]));
}
__device__ __forceinline__ void mma_s8(int* c, const uint32_t* a, const uint32_t* b) {
    asm volatile(
        "mma.sync.aligned.m16n8k32.row.col.s32.s8.s8.s32 "
        "{%0,%1,%2,%3},{%4,%5,%6,%7},{%8,%9},{%0,%1,%2,%3};"
        : "+r"(c[0]), "+r"(c[1]), "+r"(c[2]), "+r"(c[3])
        : "r"(a[0]), "r"(a[1]), "r"(a[2]), "r"(a[3]), "r"(b[0]), "r"(b[1]));
}

// ---------------- bf16 tensor-core GEMM (NN only; verified R16 lineage) ----------------
template<int OUTB>
__global__ __launch_bounds__(256, 1)
void gemm_bf(const bf16* __restrict__ A, const bf16* __restrict__ B,
             const float* __restrict__ bias, const float* __restrict__ resid,
             void* __restrict__ Cv,
             int K, int ldA, int ldB, int ldC,
             float scale, int relu)
{
    extern __shared__ __align__(128) char smem[];
    const int tid  = threadIdx.x;
    const int lane = tid & 31;
    const int wid  = tid >> 5;
    const int wm   = wid >> 2;
    const int wn   = wid & 3;
    const int l7   = lane & 7;
    const int bx = blockIdx.x, by = blockIdx.y;

    A += (long long)by * BM * ldA;
    long long cbase = (long long)by * BM * ldC + (long long)bx * BN;
    B += bx * BN;

    const uint32_t sA0 = (uint32_t)__cvta_generic_to_shared(smem);
    const uint32_t sB0 = sA0 + STAGES * A_STAGE_BYTES;

    float acc[4][8][4];
#pragma unroll
    for (int i = 0; i < 4; i++)
#pragma unroll
        for (int j = 0; j < 8; j++)
#pragma unroll
            for (int r = 0; r < 4; r++) acc[i][j][r] = 0.f;

    const int rowA0 = wm * 64 + ((lane >> 3) & 1) * 8 + l7;
    const int khA   = (lane >> 4) & 1;
    const int krow0 = ((lane >> 3) & 1) * 8 + l7;
    const int nu0   = wn * 8 + ((lane >> 4) & 1);

    const int kt = K / BK;

    auto load_tile = [&](int stg, int k0) {
        uint32_t aS = sA0 + stg * A_STAGE_BYTES;
#pragma unroll
        for (int i = 0; i < 4; i++) {
            int idx = tid + i * 256;
            int r = idx >> 3, u = idx & 7;
            cp16(aS + r * 128 + (uint32_t)((u ^ (r & 7)) << 4),
                 A + (long long)r * ldA + k0 + u * 8);
        }
        uint32_t bS = sB0 + stg * B_STAGE_BYTES;
#pragma unroll
        for (int i = 0; i < 8; i++) {
            int idx = tid + i * 256;
            int k = idx >> 5, u = idx & 31;
            cp16(bS + k * 512 + (uint32_t)((u ^ (k & 7)) << 4),
                 B + (long long)(k0 + k) * ldB + u * 8);
        }
        asm volatile("cp.async.commit_group;");
    };

    load_tile(0, 0);
    load_tile(1, BK);
    load_tile(2, 2 * BK);

    for (int t = 0; t < kt; t++) {
        int rem = kt - 1 - t;
        if (rem >= 2)      asm volatile("cp.async.wait_group 2;");
        else if (rem == 1) asm volatile("cp.async.wait_group 1;");
        else               asm volatile("cp.async.wait_group 0;");
        __syncthreads();

        if (t + 3 < kt) load_tile((t + 3) & 3, (t + 3) * BK);

        const int stg = t & 3;
        const uint32_t aS = sA0 + stg * A_STAGE_BYTES;
        const uint32_t bS = sB0 + stg * B_STAGE_BYTES;
        const uint32_t aFrag = aS + rowA0 * 128;

        uint32_t a[2][4][4], b[2][8][2];
        auto load_frag = [&](int ks, int fb) {
            const uint32_t auoff = (uint32_t)(((2 * ks + khA) ^ l7) << 4);
#pragma unroll
            for (int i = 0; i < 4; i++)
                ldsm4(a[fb][i], aFrag + i * 2048 + auoff);
            uint32_t kb = bS + (ks * 16 + krow0) * 512;
#pragma unroll
            for (int jb = 0; jb < 4; jb++) {
                uint32_t t0[4];
                ldsm4t(t0, kb + (uint32_t)(((nu0 + 2 * jb) ^ l7) << 4));
                b[fb][2 * jb][0] = t0[0]; b[fb][2 * jb][1] = t0[1];
                b[fb][2 * jb + 1][0] = t0[2]; b[fb][2 * jb + 1][1] = t0[3];
            }
        };

        load_frag(0, 0);
#pragma unroll
        for (int ks = 0; ks < 4; ks++) {
            const int fb = ks & 1;
            if (ks < 3) load_frag(ks + 1, fb ^ 1);
#pragma unroll
            for (int i = 0; i < 4; i++)
#pragma unroll
                for (int j = 0; j < 8; j++)
                    mma16(acc[i][j], a[fb][i], b[fb][j]);
        }
    }

    const int gr = lane >> 2, tg = lane & 3;
#pragma unroll
    for (int i = 0; i < 4; i++) {
        int r0 = wm * 64 + i * 16 + gr;
#pragma unroll
        for (int j = 0; j < 8; j++) {
            int col = wn * 64 + j * 8 + 2 * tg;
            float b0 = 0.f, b1 = 0.f;
            if (bias) {
                b0 = bias[bx * BN + col];
                b1 = bias[bx * BN + col + 1];
            }
            float v0 = acc[i][j][0] * scale + b0;
            float v1 = acc[i][j][1] * scale + b1;
            float v2 = acc[i][j][2] * scale + b0;
            float v3 = acc[i][j][3] * scale + b1;
            if (relu) {
                v0 = fmaxf(v0, 0.f); v1 = fmaxf(v1, 0.f);
                v2 = fmaxf(v2, 0.f); v3 = fmaxf(v3, 0.f);
            }
            if (OUTB) {
                bf16* C = (bf16*)Cv;
                __nv_bfloat162 p0, p1;
                p0.x = __float2bfloat16(v0); p0.y = __float2bfloat16(v1);
                p1.x = __float2bfloat16(v2); p1.y = __float2bfloat16(v3);
                *(__nv_bfloat162*)(C + cbase + (long long)r0 * ldC + col)       = p0;
                *(__nv_bfloat162*)(C + cbase + (long long)(r0 + 8) * ldC + col) = p1;
            } else {
                if (resid) {
                    float2 q0 = *(const float2*)(resid + cbase + (long long)r0 * ldC + col);
                    float2 q1 = *(const float2*)(resid + cbase + (long long)(r0 + 8) * ldC + col);
                    v0 += q0.x; v1 += q0.y; v2 += q1.x; v3 += q1.y;
                }
                float* C = (float*)Cv;
                *(float2*)(C + cbase + (long long)r0 * ldC + col)       = make_float2(v0, v1);
                *(float2*)(C + cbase + (long long)(r0 + 8) * ldC + col) = make_float2(v2, v3);
            }
        }
    }
}

// ---------------- s8 tensor-core GEMM (NT only): C = (A s8 @ B^T s8) deq ----------------
// A: [M,K] s8 row-major. B: [N,K] s8 row-major. Per-row scales sAv, per-B-row scales sBv.
// OUTB=1: C bf16; OUTB=0: C f32. BK = 128 s8 elements (same 128B geometry).
template<int OUTB>
__global__ __launch_bounds__(256, 1)
void gemm_s8(const int8_t* __restrict__ A, const int8_t* __restrict__ B,
             const float* __restrict__ sAv, const float* __restrict__ sBv,
             void* __restrict__ Cv,
             int K, int ldA, int ldB, int ldC,
             long long sA_, long long sB_, long long sC_,
             long long ssA, long long ssB)
{
    extern __shared__ __align__(128) char smem[];
    const int tid  = threadIdx.x;
    const int lane = tid & 31;
    const int wid  = tid >> 5;
    const int wm   = wid >> 2;
    const int wn   = wid & 3;
    const int l7   = lane & 7;
    const int bx = blockIdx.x, by = blockIdx.y, bz = blockIdx.z;

    A += (long long)bz * sA_ + (long long)by * BM * ldA;
    B += (long long)bz * sB_ + (long long)bx * BN * ldB;
    sAv += (long long)bz * ssA + (long long)by * BM;
    sBv += (long long)bz * ssB + (long long)bx * BN;
    const long long cbase = (long long)bz * sC_ + (long long)by * BM * ldC + (long long)bx * BN;

    const uint32_t sA0 = (uint32_t)__cvta_generic_to_shared(smem);
    const uint32_t sB0 = sA0 + STAGES * A_STAGE_BYTES;

    int acc[4][8][4];
#pragma unroll
    for (int i = 0; i < 4; i++)
#pragma unroll
        for (int j = 0; j < 8; j++)
#pragma unroll
            for (int r = 0; r < 4; r++) acc[i][j][r] = 0;

    const int rowA0 = wm * 64 + ((lane >> 3) & 1) * 8 + l7;
    const int khA   = (lane >> 4) & 1;
    const int rowB0 = wn * 64 + ((lane >> 4) & 1) * 8 + l7;
    const int khB   = (lane >> 3) & 1;

    const int kt = K / 128;          // 128 s8 per k-tile (128B rows)

    auto load_tile = [&](int stg, int k0) {
        uint32_t aS = sA0 + stg * A_STAGE_BYTES;
#pragma unroll
        for (int i = 0; i < 4; i++) {
            int idx = tid + i * 256;
            int r = idx >> 3, u = idx & 7;
            cp16(aS + r * 128 + (uint32_t)((u ^ (r & 7)) << 4),
                 A + (long long)r * ldA + k0 + u * 16);
        }
        uint32_t bS = sB0 + stg * B_STAGE_BYTES;
#pragma unroll
        for (int i = 0; i < 8; i++) {
            int idx = tid + i * 256;
            int n = idx >> 3, u = idx & 7;
            cp16(bS + n * 128 + (uint32_t)((u ^ (n & 7)) << 4),
                 B + (long long)n * ldB + k0 + u * 16);
        }
        asm volatile("cp.async.commit_group;");
    };

    load_tile(0, 0);
    load_tile(1, 128);
    load_tile(2, 256);

    for (int t = 0; t < kt; t++) {
        int rem = kt - 1 - t;
        if (rem >= 2)      asm volatile("cp.async.wait_group 2;");
        else if (rem == 1) asm volatile("cp.async.wait_group 1;");
        else               asm volatile("cp.async.wait_group 0;");
        __syncthreads();

        if (t + 3 < kt) load_tile((t + 3) & 3, (t + 3) * 128);

        const int stg = t & 3;
        const uint32_t aFrag = sA0 + stg * A_STAGE_BYTES + rowA0 * 128;
        const uint32_t bFrag = sB0 + stg * B_STAGE_BYTES + rowB0 * 128;

        uint32_t a[2][4][4], b[2][8][2];
        auto load_frag = [&](int ks, int fb) {
            const uint32_t auoff = (uint32_t)(((2 * ks + khA) ^ l7) << 4);
#pragma unroll
            for (int i = 0; i < 4; i++)
                ldsm4(a[fb][i], aFrag + i * 2048 + auoff);
            const uint32_t buoff = (uint32_t)(((2 * ks + khB) ^ l7) << 4);
#pragma unroll
            for (int jb = 0; jb < 4; jb++) {
                uint32_t t0[4];
                ldsm4(t0, bFrag + jb * 2048 + buoff);
                b[fb][2 * jb][0] = t0[0]; b[fb][2 * jb][1] = t0[1];
                b[fb][2 * jb + 1][0] = t0[2]; b[fb][2 * jb + 1][1] = t0[3];
            }
        };

        load_frag(0, 0);
#pragma unroll
        for (int ks = 0; ks < 4; ks++) {
            const int fb = ks & 1;
            if (ks < 3) load_frag(ks + 1, fb ^ 1);
#pragma unroll
            for (int i = 0; i < 4; i++)
#pragma unroll
                for (int j = 0; j < 8; j++)
                    mma_s8(acc[i][j], a[fb][i], b[fb][j]);
        }
    }

    const int gr = lane >> 2, tg = lane & 3;
#pragma unroll
    for (int i = 0; i < 4; i++) {
        int r0 = wm * 64 + i * 16 + gr;
        float sa0 = sAv[r0], sa1 = sAv[r0 + 8];
#pragma unroll
        for (int j = 0; j < 8; j++) {
            int col = wn * 64 + j * 8 + 2 * tg;
            float sb0 = sBv[col], sb1 = sBv[col + 1];
            float v0 = (float)acc[i][j][0] * sa0 * sb0;
            float v1 = (float)acc[i][j][1] * sa0 * sb1;
            float v2 = (float)acc[i][j][2] * sa1 * sb0;
            float v3 = (float)acc[i][j][3] * sa1 * sb1;
            if (OUTB) {
                bf16* C = (bf16*)Cv;
                __nv_bfloat162 p0, p1;
                p0.x = __float2bfloat16(v0); p0.y = __float2bfloat16(v1);
                p1.x = __float2bfloat16(v2); p1.y = __float2bfloat16(v3);
                *(__nv_bfloat162*)(C + cbase + (long long)r0 * ldC + col)       = p0;
                *(__nv_bfloat162*)(C + cbase + (long long)(r0 + 8) * ldC + col) = p1;
            } else {
                float* C = (float*)Cv;
                *(float2*)(C + cbase + (long long)r0 * ldC + col)       = make_float2(v0, v1);
                *(float2*)(C + cbase + (long long)(r0 + 8) * ldC + col) = make_float2(v2, v3);
            }
        }
    }
}

// ---------------- row softmax: f32 in, s8 out + row scale, with pre-scale --------
__global__ __launch_bounds__(256)
void softmax_q(const float* __restrict__ sc, int8_t* __restrict__ pq,
               float* __restrict__ ps, float scale)
{
    __shared__ float redm[8], reds[8];
    const long long row = blockIdx.x;
    const float* p = sc + row * (long long)S_;
    int8_t* o = pq + row * (long long)S_;
    const int tid = threadIdx.x, lane = tid & 31, wid = tid >> 5;

    float v[8];
    float m = -1e30f;
#pragma unroll
    for (int i = 0; i < 8; i++) {
        v[i] = p[tid + i * 256] * scale;
        m = fmaxf(m, v[i]);
    }
#pragma unroll
    for (int s = 16; s > 0; s >>= 1)
        m = fmaxf(m, __shfl_xor_sync(0xffffffffu, m, s));
    if (lane == 0) redm[wid] = m;
    __syncthreads();
    float mm = redm[0];
#pragma unroll
    for (int i = 1; i < 8; i++) mm = fmaxf(mm, redm[i]);

    float s = 0.f;
#pragma unroll
    for (int i = 0; i < 8; i++) { v[i] = expf(v[i] - mm); s += v[i]; }
#pragma unroll
    for (int t2 = 16; t2 > 0; t2 >>= 1)
        s += __shfl_xor_sync(0xffffffffu, s, t2);
    if (lane == 0) reds[wid] = s;
    __syncthreads();
    float ss = reds[0];
#pragma unroll
    for (int i = 1; i < 8; i++) ss += reds[i];
    float inv = 1.f / ss;
    if (tid == 0) ps[row] = inv * (1.f / 127.f);   // P = v*inv; max v = 1
#pragma unroll
    for (int i = 0; i < 8; i++) {
        int q = __float2int_rn(v[i] * 127.f);      // p/scale = 127*v
        o[tid + i * 256] = (int8_t)min(127, q);
    }
}

// ---------------- layernorm: x = LN(s), writes f32 + bf16 (s has residual) ------
__global__ __launch_bounds__(128)
void ln_kernel(float* __restrict__ x, bf16* __restrict__ xb,
               const float* __restrict__ srow,
               const float* __restrict__ g, const float* __restrict__ b)
{
    __shared__ float red[4], red2[4];
    const long long row = blockIdx.x;
    const int tid = threadIdx.x, lane = tid & 31, wid = tid >> 5;
    float* px = x + row * (long long)D_;
    bf16* pb  = xb + row * (long long)D_;
    const float* ps = srow + row * (long long)D_;

    float v[4];
    float s = 0.f;
#pragma unroll
    for (int i = 0; i < 4; i++) {
        v[i] = ps[tid + i * 128];
        s += v[i];
    }
#pragma unroll
    for (int t2 = 16; t2 > 0; t2 >>= 1)
        s += __shfl_xor_sync(0xffffffffu, s, t2);
    if (lane == 0) red[wid] = s;
    __syncthreads();
    const float mu = (red[0] + red[1] + red[2] + red[3]) * (1.f / D_);

    float sq = 0.f;
#pragma unroll
    for (int i = 0; i < 4; i++) { float d = v[i] - mu; sq += d * d; }
#pragma unroll
    for (int t2 = 16; t2 > 0; t2 >>= 1)
        sq += __shfl_xor_sync(0xffffffffu, sq, t2);
    if (lane == 0) red2[wid] = sq;
    __syncthreads();
    const float rstd = rsqrtf((red2[0] + red2[1] + red2[2] + red2[3]) * (1.f / D_) + 1e-5f);
#pragma unroll
    for (int i = 0; i < 4; i++) {
        int c = tid + i * 128;
        float y = (v[i] - mu) * rstd * g[c] + b[c];
        px[c] = y;
        pb[c] = __float2bfloat16(y);
    }
}

// ---------------- mean-pool over S then dot with clf_w ----------------
__global__ __launch_bounds__(256)
void pool_kernel(const float* __restrict__ x, const float* __restrict__ w,
                 const float* __restrict__ cb, float* __restrict__ out)
{
    __shared__ float red[256];
    const int b = blockIdx.x;
    const int tid = threadIdx.x;
    const float* p = x + (long long)b * S_ * D_;
    float acc = 0.f;
    for (int i = tid; i < S_ * D_; i += 256)
        acc += p[i] * w[i & (D_ - 1)];
    red[tid] = acc; __syncthreads();
    for (int o = 128; o > 0; o >>= 1) {
        if (tid < o) red[tid] += red[tid + o];
        __syncthreads();
    }
    if (tid == 0) out[b] = red[0] * (1.f / (float)S_) + cb[0];
}

// ---------------- host orchestration ----------------
extern "C" void kernel_launch(void* const* d_in, const int* in_sizes, int n_in,
                              void* d_out, int out_size)
{
    (void)in_sizes; (void)n_in; (void)out_size;
    const int*   tokens = (const int*)  d_in[0];
    const float* emb    = (const float*)d_in[1];
    const float* Wq     = (const float*)d_in[2];
    const float* bq     = (const float*)d_in[3];
    const float* Wk     = (const float*)d_in[4];
    const float* bk     = (const float*)d_in[5];
    const float* Wv     = (const float*)d_in[6];
    const float* bv     = (const float*)d_in[7];
    const float* Wo     = (const float*)d_in[8];
    const float* bo     = (const float*)d_in[9];
    const float* W1     = (const float*)d_in[10];
    const float* b1     = (const float*)d_in[11];
    const float* W2     = (const float*)d_in[12];
    const float* b2     = (const float*)d_in[13];
    const float* ln1g   = (const float*)d_in[14];
    const float* ln1b   = (const float*)d_in[15];
    const float* ln2g   = (const float*)d_in[16];
    const float* ln2b   = (const float*)d_in[17];
    const float* clfw   = (const float*)d_in[18];
    const float* clfb   = (const float*)d_in[19];
    float* out = (float*)d_out;

    float *x, *r, *sc, *bqkv, *qs, *ks, *ps, *vs;
    bf16 *xb, *qkv, *tb, *hb;
    bf16 *wqkv, *wob, *w1b, *w2b;
    int8_t *qq, *kq, *pq, *vtq;
    int *vcm;
    cudaGetSymbolAddress((void**)&x,    g_x);
    cudaGetSymbolAddress((void**)&r,    g_r);
    cudaGetSymbolAddress((void**)&sc,   g_sc);
    cudaGetSymbolAddress((void**)&xb,   g_xb);
    cudaGetSymbolAddress((void**)&qkv,  g_qkv);
    cudaGetSymbolAddress((void**)&tb,   g_tb);
    cudaGetSymbolAddress((void**)&hb,   g_hb);
    cudaGetSymbolAddress((void**)&pq,   g_pq);
    cudaGetSymbolAddress((void**)&ps,   g_ps);
    cudaGetSymbolAddress((void**)&qq,   g_qq);
    cudaGetSymbolAddress((void**)&qs,   g_qs);
    cudaGetSymbolAddress((void**)&kq,   g_kq);
    cudaGetSymbolAddress((void**)&ks,   g_ks);
    cudaGetSymbolAddress((void**)&vtq,  g_vtq);
    cudaGetSymbolAddress((void**)&vcm,  g_vcm);
    cudaGetSymbolAddress((void**)&vs,   g_vs);
    cudaGetSymbolAddress((void**)&wqkv, g_wqkv);
    cudaGetSymbolAddress((void**)&bqkv, g_bqkv);
    cudaGetSymbolAddress((void**)&wob,  g_wob);
    cudaGetSymbolAddress((void**)&w1b,  g_w1b);
    cudaGetSymbolAddress((void**)&w2b,  g_w2b);

    cudaFuncSetAttribute(gemm_bf<1>, cudaFuncAttributeMaxDynamicSharedMemorySize, SMEM_BYTES);
    cudaFuncSetAttribute(gemm_bf<0>, cudaFuncAttributeMaxDynamicSharedMemorySize, SMEM_BYTES);
    cudaFuncSetAttribute(gemm_s8<1>, cudaFuncAttributeMaxDynamicSharedMemorySize, SMEM_BYTES);
    cudaFuncSetAttribute(gemm_s8<0>, cudaFuncAttributeMaxDynamicSharedMemorySize, SMEM_BYTES);

    // weight conversion / concatenation (idempotent per launch)
    cvt_qkv_w<<<(L_ * D_ * D_) / 256, 256>>>(Wq, Wk, Wv, wqkv);
    cvt_qkv_b<<<(L_ * D_) / 256, 256>>>(bq, bk, bv, bqkv);
    cvt_bf<<<(L_ * D_ * D_) / 256, 256>>>(Wo, wob);
    cvt_bf<<<(L_ * D_ * F_) / 256, 256>>>(W1, w1b);
    cvt_bf<<<(L_ * D_ * F_) / 256, 256>>>(W2, w2b);

    embed_kernel<<<(BS_ * D_) / 256, 256>>>(tokens, emb, x, xb);

    const dim3 gQKV(D3_ / BN, BS_ / BM, 1);
    const dim3 gProj(D_ / BN, BS_ / BM, 1);
    const dim3 gScores(S_ / BN, S_ / BM, B_);
    const dim3 gAV(D_ / BN, S_ / BM, B_);
    const dim3 gF1(F_ / BN, BS_ / BM, 1);
    const float kscale = 0.044194173824159216f;  // 1/sqrt(512)

    for (int l = 0; l < L_; l++) {
        const bf16* Wqkv_l = wqkv + (size_t)l * D_ * D3_;
        const float* bqkv_l = bqkv + (size_t)l * D3_;
        const bf16* Wo_l = wob + (size_t)l * D_ * D_;
        const bf16* W1_l = w1b + (size_t)l * D_ * F_;
        const bf16* W2_l = w2b + (size_t)l * F_ * D_;
        const float* bo_l = bo + (size_t)l * D_;
        const float* b1_l = b1 + (size_t)l * F_;
        const float* b2_l = b2 + (size_t)l * D_;

        // fused QKV (bf16): qkv[BS,1536] = xb @ Wqkv + bqkv
        gemm_bf<1><<<gQKV, 256, SMEM_BYTES>>>(xb, Wqkv_l, bqkv_l, nullptr, qkv,
                                              D_, D_, D3_, D3_, 1.f, 0);

        // quantize Q,K rows; V columns (transposed)
        quant_rows<<<BS_, 128>>>(qkv, D3_, 0,    qq, qs);
        quant_rows<<<BS_, 128>>>(qkv, D3_, D_,   kq, ks);
        cudaMemsetAsync(vcm, 0, B_ * D_ * sizeof(int));
        vcolmax<<<dim3(S_ / 128, B_), 256>>>(qkv, vcm);
        vtquant<<<dim3(S_ / 64, D_ / 64, B_), 256>>>(qkv, vcm, vtq);
        vscale_fin<<<(B_ * D_) / 256, 256>>>(vcm, vs);

        // scores[b] = Q_b @ K_b^T (s8; f32 out; kscale applied in softmax)
        gemm_s8<0><<<gScores, 256, SMEM_BYTES>>>(qq, kq, qs, ks, sc,
                                                 D_, D_, D_, S_,
                                                 (long long)S_ * D_, (long long)S_ * D_,
                                                 (long long)S_ * S_, S_, S_);
        softmax_q<<<B_ * S_, 256>>>(sc, pq, ps, kscale);

        // t[b] = P_b @ V_b  via  P s8 @ (V^T)^T s8 -> bf16
        gemm_s8<1><<<gAV, 256, SMEM_BYTES>>>(pq, vtq, ps, vs, tb,
                                             S_, S_, S_, D_,
                                             (long long)S_ * S_, (long long)D_ * S_,
                                             (long long)S_ * D_, S_, D_);

        // r = x + (t @ Wo + bo)  (bf16 GEMM, residual fused)
        gemm_bf<0><<<gProj, 256, SMEM_BYTES>>>(tb, Wo_l, bo_l, x, r,
                                               D_, D_, D_, D_, 1.f, 0);
        ln_kernel<<<BS_, 128>>>(x, xb, r, ln1g + (size_t)l * D_, ln1b + (size_t)l * D_);

        // FFN (bf16)
        gemm_bf<1><<<gF1, 256, SMEM_BYTES>>>(xb, W1_l, b1_l, nullptr, hb,
                                             D_, D_, F_, F_, 1.f, 1);
        gemm_bf<0><<<gProj, 256, SMEM_BYTES>>>(hb, W2_l, b2_l, x, r,
                                               F_, F_, D_, D_, 1.f, 0);
        ln_kernel<<<BS_, 128>>>(x, xb, r, ln2g + (size_t)l * D_, ln2b + (size_t)l * D_);
    }

    pool_kernel<<<B_, 256>>>(x, clfw, clfb, out);
}